// round 1
// baseline (speedup 1.0000x reference)
#include <cuda_runtime.h>
#include <math.h>

#define NTOK 65536
#define DIM  512
#define KCB  512
#define NDsz ((size_t)NTOK * (size_t)DIM)
#define NKsz ((size_t)NTOK * (size_t)KCB)

// ---- scratch (device globals: allocation-free) ----
__device__ float  g_X[NDsz];      // mean-layer output x  [N, D]
__device__ float  g_Z[NKsz];      // z_logvar -> unnorm probs -> norm probs [N, K]
__device__ float  g_xnorm[NTOK];
__device__ float  g_enorm[KCB];
__device__ float  g_colsum[KCB];
__device__ double g_sse;

// ---------------- init ----------------
__global__ void init_kernel() {
    int t = threadIdx.x;
    if (t < KCB) g_colsum[t] = 0.f;
    if (t == 0)  g_sse = 0.0;
}

// ---- squared row norms of a [rows, 512] row-major matrix, 1 warp / row ----
// mode 0: A=ext (embedding) -> g_enorm ; mode 1: A=g_X -> g_xnorm
__global__ void rownorm2_kernel(const float* __restrict__ Aext, int mode, int rows) {
    int lane = threadIdx.x & 31;
    int warp = threadIdx.x >> 5;
    int row  = blockIdx.x * 8 + warp;
    if (row >= rows) return;
    const float* A = (mode == 0) ? Aext : g_X;
    const float* p = A + (size_t)row * 512;
    float s = 0.f;
#pragma unroll
    for (int c = 0; c < 4; c++) {
        float4 v = *(const float4*)(p + c * 128 + lane * 4);
        s += v.x * v.x + v.y * v.y + v.z * v.z + v.w * v.w;
    }
#pragma unroll
    for (int o = 16; o; o >>= 1) s += __shfl_xor_sync(0xffffffffu, s, o);
    if (lane == 0) {
        if (mode == 0) g_enorm[row] = s;
        else           g_xnorm[row] = s;
    }
}

// ---------------- GEMM 1&2: C = A @ B + bias (NN, all dims %128/%8) ------
// aflag: 0 -> A=Aext (inputs), 1 -> A=g_X ; cflag: 0 -> C=g_X, 1 -> C=g_Z
__global__ __launch_bounds__(256) void sgemm_bias_kernel(
    const float* __restrict__ Aext, const float* __restrict__ B,
    const float* __restrict__ bias, int aflag, int cflag,
    int M, int N, int K)
{
    __shared__ __align__(16) float As[8][128];
    __shared__ __align__(16) float Bs[8][128];
    const int tid  = threadIdx.x;
    const int bm   = blockIdx.y * 128;
    const int bn   = blockIdx.x * 128;
    const int arow = tid >> 1, acol = (tid & 1) * 4;
    const int brow = tid >> 5, bcol = (tid & 31) * 4;
    const int trow = (tid >> 4) * 8, tcol = (tid & 15) * 8;

    const float* A = aflag ? g_X : Aext;
    float*       C = cflag ? g_Z : g_X;

    float acc[8][8];
#pragma unroll
    for (int i = 0; i < 8; i++)
#pragma unroll
        for (int j = 0; j < 8; j++) acc[i][j] = 0.f;

    const float* Ap = A + (size_t)(bm + arow) * K + acol;
    const float* Bp = B + (size_t)brow * N + bn + bcol;

    for (int k0 = 0; k0 < K; k0 += 8) {
        float4 av = *(const float4*)(Ap + k0);
        As[acol + 0][arow] = av.x; As[acol + 1][arow] = av.y;
        As[acol + 2][arow] = av.z; As[acol + 3][arow] = av.w;
        *(float4*)&Bs[brow][bcol] = *(const float4*)(Bp + (size_t)k0 * N);
        __syncthreads();
#pragma unroll
        for (int kk = 0; kk < 8; kk++) {
            float4 a0 = *(const float4*)&As[kk][trow];
            float4 a1 = *(const float4*)&As[kk][trow + 4];
            float4 b0 = *(const float4*)&Bs[kk][tcol];
            float4 b1 = *(const float4*)&Bs[kk][tcol + 4];
            float ar[8] = {a0.x, a0.y, a0.z, a0.w, a1.x, a1.y, a1.z, a1.w};
            float br[8] = {b0.x, b0.y, b0.z, b0.w, b1.x, b1.y, b1.z, b1.w};
#pragma unroll
            for (int i = 0; i < 8; i++)
#pragma unroll
                for (int j = 0; j < 8; j++)
                    acc[i][j] = fmaf(ar[i], br[j], acc[i][j]);
        }
        __syncthreads();
    }

    float4 bv0 = *(const float4*)(bias + bn + tcol);
    float4 bv1 = *(const float4*)(bias + bn + tcol + 4);
    float bb[8] = {bv0.x, bv0.y, bv0.z, bv0.w, bv1.x, bv1.y, bv1.z, bv1.w};
#pragma unroll
    for (int i = 0; i < 8; i++) {
        size_t row = (size_t)(bm + trow + i);
        float* cp = C + row * N + bn + tcol;
        float4 v0 = {acc[i][0] + bb[0], acc[i][1] + bb[1], acc[i][2] + bb[2], acc[i][3] + bb[3]};
        float4 v1 = {acc[i][4] + bb[4], acc[i][5] + bb[5], acc[i][6] + bb[6], acc[i][7] + bb[7]};
        *(float4*)cp       = v0;
        *(float4*)(cp + 4) = v1;
    }
}

// ------- GEMM 3: dots = g_X @ E^T, epilogue -> unnormalized prob into g_Z --
__global__ __launch_bounds__(256) void gemm_prob_kernel(const float* __restrict__ E)
{
    __shared__ __align__(16) float As[8][128];
    __shared__ __align__(16) float Bs[8][128];
    const int tid  = threadIdx.x;
    const int bm   = blockIdx.y * 128;   // token rows
    const int bn   = blockIdx.x * 128;   // codebook cols
    const int arow = tid >> 1, acol = (tid & 1) * 4;
    const int trow = (tid >> 4) * 8, tcol = (tid & 15) * 8;

    float acc[8][8];
#pragma unroll
    for (int i = 0; i < 8; i++)
#pragma unroll
        for (int j = 0; j < 8; j++) acc[i][j] = 0.f;

    const float* Ap = g_X + (size_t)(bm + arow) * DIM + acol;
    const float* Ep = E   + (size_t)(bn + arow) * DIM + acol;

    for (int k0 = 0; k0 < DIM; k0 += 8) {
        float4 av = *(const float4*)(Ap + k0);
        As[acol + 0][arow] = av.x; As[acol + 1][arow] = av.y;
        As[acol + 2][arow] = av.z; As[acol + 3][arow] = av.w;
        float4 ev = *(const float4*)(Ep + k0);
        Bs[acol + 0][arow] = ev.x; Bs[acol + 1][arow] = ev.y;
        Bs[acol + 2][arow] = ev.z; Bs[acol + 3][arow] = ev.w;
        __syncthreads();
#pragma unroll
        for (int kk = 0; kk < 8; kk++) {
            float4 a0 = *(const float4*)&As[kk][trow];
            float4 a1 = *(const float4*)&As[kk][trow + 4];
            float4 b0 = *(const float4*)&Bs[kk][tcol];
            float4 b1 = *(const float4*)&Bs[kk][tcol + 4];
            float ar[8] = {a0.x, a0.y, a0.z, a0.w, a1.x, a1.y, a1.z, a1.w};
            float br[8] = {b0.x, b0.y, b0.z, b0.w, b1.x, b1.y, b1.z, b1.w};
#pragma unroll
            for (int i = 0; i < 8; i++)
#pragma unroll
                for (int j = 0; j < 8; j++)
                    acc[i][j] = fmaf(ar[i], br[j], acc[i][j]);
        }
        __syncthreads();
    }

    float4 e0 = *(const float4*)(g_enorm + bn + tcol);
    float4 e1 = *(const float4*)(g_enorm + bn + tcol + 4);
    float er[8] = {e0.x, e0.y, e0.z, e0.w, e1.x, e1.y, e1.z, e1.w};
#pragma unroll
    for (int i = 0; i < 8; i++) {
        size_t row = (size_t)(bm + trow + i);
        float xn = g_xnorm[row];
        float* zp = g_Z + row * KCB + bn + tcol;
        float4 z0 = *(const float4*)zp;
        float4 z1 = *(const float4*)(zp + 4);
        float zr[8] = {z0.x, z0.y, z0.z, z0.w, z1.x, z1.y, z1.z, z1.w};
        float pr[8];
#pragma unroll
        for (int j = 0; j < 8; j++) {
            float dist = xn + er[j] - 2.f * acc[i][j];
            float dd   = dist * (1.f / 400.f);
            float sm   = expf(-2.f * zr[j]);     // smooth
            pr[j]      = expf(zr[j] - 0.5f * dd * sm);  // exp(-d*sm/2)/sqrt(sm)
        }
        float4 p0 = {pr[0], pr[1], pr[2], pr[3]};
        float4 p1 = {pr[4], pr[5], pr[6], pr[7]};
        *(float4*)zp       = p0;
        *(float4*)(zp + 4) = p1;
    }
}

// --- normalize rows of g_Z in place, mirror to Pout (8B-aligned), colsums ---
__global__ __launch_bounds__(256) void normalize_kernel(float* __restrict__ Pout)
{
    __shared__ float scol[512];
    int tid = threadIdx.x, lane = tid & 31, warp = tid >> 5;
    for (int i = tid; i < 512; i += 256) scol[i] = 0.f;
    __syncthreads();

    int row0 = blockIdx.x * 32 + warp * 4;
    float local[16];
#pragma unroll
    for (int i = 0; i < 16; i++) local[i] = 0.f;

    for (int r = 0; r < 4; r++) {
        size_t base = (size_t)(row0 + r) * KCB;
        float4 v[4];
        float s = 0.f;
#pragma unroll
        for (int c = 0; c < 4; c++) {
            v[c] = *(const float4*)(g_Z + base + c * 128 + lane * 4);
            s += v[c].x + v[c].y + v[c].z + v[c].w;
        }
#pragma unroll
        for (int o = 16; o; o >>= 1) s += __shfl_xor_sync(0xffffffffu, s, o);
        float inv = 1.f / s;
#pragma unroll
        for (int c = 0; c < 4; c++) {
            v[c].x *= inv; v[c].y *= inv; v[c].z *= inv; v[c].w *= inv;
            *(float4*)(g_Z + base + c * 128 + lane * 4) = v[c];
            float2 lo = {v[c].x, v[c].y};
            float2 hi = {v[c].z, v[c].w};
            *(float2*)(Pout + base + c * 128 + lane * 4)     = lo;
            *(float2*)(Pout + base + c * 128 + lane * 4 + 2) = hi;
            local[c * 4 + 0] += v[c].x; local[c * 4 + 1] += v[c].y;
            local[c * 4 + 2] += v[c].z; local[c * 4 + 3] += v[c].w;
        }
    }
#pragma unroll
    for (int c = 0; c < 4; c++)
#pragma unroll
        for (int t = 0; t < 4; t++)
            atomicAdd(&scol[c * 128 + lane * 4 + t], local[c * 4 + t]);
    __syncthreads();
    for (int i = tid; i < 512; i += 256) atomicAdd(&g_colsum[i], scol[i]);
}

// ---- GEMM 4: quantized = probs(g_Z) @ E ; qst + SSE epilogue --------------
__global__ __launch_bounds__(256) void gemm_quant_kernel(
    const float* __restrict__ E, const float* __restrict__ IN,
    float* __restrict__ Q)
{
    __shared__ __align__(16) float As[8][128];
    __shared__ __align__(16) float Bs[8][128];
    const int tid  = threadIdx.x;
    const int bm   = blockIdx.y * 128;
    const int bn   = blockIdx.x * 128;
    const int arow = tid >> 1, acol = (tid & 1) * 4;
    const int brow = tid >> 5, bcol = (tid & 31) * 4;
    const int trow = (tid >> 4) * 8, tcol = (tid & 15) * 8;

    float acc[8][8];
#pragma unroll
    for (int i = 0; i < 8; i++)
#pragma unroll
        for (int j = 0; j < 8; j++) acc[i][j] = 0.f;

    const float* Ap = g_Z + (size_t)(bm + arow) * KCB + acol;
    const float* Bp = E   + (size_t)brow * DIM + bn + bcol;

    for (int k0 = 0; k0 < KCB; k0 += 8) {
        float4 av = *(const float4*)(Ap + k0);
        As[acol + 0][arow] = av.x; As[acol + 1][arow] = av.y;
        As[acol + 2][arow] = av.z; As[acol + 3][arow] = av.w;
        *(float4*)&Bs[brow][bcol] = *(const float4*)(Bp + (size_t)k0 * DIM);
        __syncthreads();
#pragma unroll
        for (int kk = 0; kk < 8; kk++) {
            float4 a0 = *(const float4*)&As[kk][trow];
            float4 a1 = *(const float4*)&As[kk][trow + 4];
            float4 b0 = *(const float4*)&Bs[kk][tcol];
            float4 b1 = *(const float4*)&Bs[kk][tcol + 4];
            float ar[8] = {a0.x, a0.y, a0.z, a0.w, a1.x, a1.y, a1.z, a1.w};
            float br[8] = {b0.x, b0.y, b0.z, b0.w, b1.x, b1.y, b1.z, b1.w};
#pragma unroll
            for (int i = 0; i < 8; i++)
#pragma unroll
                for (int j = 0; j < 8; j++)
                    acc[i][j] = fmaf(ar[i], br[j], acc[i][j]);
        }
        __syncthreads();
    }

    double lsse = 0.0;
#pragma unroll
    for (int i = 0; i < 8; i++) {
        size_t row = (size_t)(bm + trow + i);
        const float* inp = IN + row * DIM + bn + tcol;
        float* qp = Q + row * DIM + bn + tcol;   // 4B-aligned only -> scalar stores
        float4 in0 = *(const float4*)inp;
        float4 in1 = *(const float4*)(inp + 4);
        float inr[8] = {in0.x, in0.y, in0.z, in0.w, in1.x, in1.y, in1.z, in1.w};
#pragma unroll
        for (int j = 0; j < 8; j++) {
            float q = acc[i][j];
            float diff = q - inr[j];
            lsse += (double)(diff * diff);
            qp[j] = inr[j] + (q - inr[j]);   // straight-through, reference rounding
        }
    }
    __shared__ double sred[256];
    sred[tid] = lsse;
    __syncthreads();
    for (int s = 128; s; s >>= 1) {
        if (tid < s) sred[tid] += sred[tid + s];
        __syncthreads();
    }
    if (tid == 0) atomicAdd(&g_sse, sred[0]);
}

// ---------------- finalize scalars ----------------
__global__ void finalize_kernel(float* __restrict__ loss_ptr,
                                float* __restrict__ ppl_ptr)
{
    __shared__ float sred[512];
    int tid = threadIdx.x;
    float avg = g_colsum[tid] * (1.f / (float)NTOK);
    sred[tid] = avg * logf(avg + 1e-10f);
    __syncthreads();
    for (int s = 256; s; s >>= 1) {
        if (tid < s) sred[tid] += sred[tid + s];
        __syncthreads();
    }
    if (tid == 0) {
        *ppl_ptr  = expf(-sred[0]);
        *loss_ptr = (float)(1.25 * g_sse * (1.0 / ((double)NTOK * (double)DIM)));
    }
}

extern "C" void kernel_launch(void* const* d_in, const int* in_sizes, int n_in,
                              void* d_out, int out_size)
{
    (void)in_sizes; (void)n_in; (void)out_size;
    const float* x   = (const float*)d_in[0];  // inputs  [B,T,D] -> [N,D]
    const float* mW  = (const float*)d_in[1];  // mean_W  [D,D]
    const float* mb  = (const float*)d_in[2];  // mean_b  [D]
    const float* lW  = (const float*)d_in[3];  // logvar_W [D,K]
    const float* lb  = (const float*)d_in[4];  // logvar_b [K]
    const float* emb = (const float*)d_in[5];  // embedding [K,D]

    float* o         = (float*)d_out;
    float* loss_ptr  = o;                        // scalar
    float* q_ptr     = o + 1;                    // [N,D]
    float* ppl_ptr   = o + 1 + NDsz;             // scalar
    float* probs_ptr = o + 2 + NDsz;             // [N,K]

    dim3 g4(KCB / 128, NTOK / 128);              // (4, 512)

    init_kernel<<<1, 512>>>();
    rownorm2_kernel<<<KCB / 8, 256>>>(emb, 0, KCB);                 // g_enorm
    sgemm_bias_kernel<<<g4, 256>>>(x, mW, mb, 0, 0, NTOK, DIM, DIM);   // g_X = x@mW+mb
    rownorm2_kernel<<<NTOK / 8, 256>>>(nullptr, 1, NTOK);           // g_xnorm
    sgemm_bias_kernel<<<g4, 256>>>(nullptr, lW, lb, 1, 1, NTOK, KCB, DIM); // g_Z = x@lW+lb
    gemm_prob_kernel<<<g4, 256>>>(emb);                             // g_Z := unnorm prob
    normalize_kernel<<<NTOK / 32, 256>>>(probs_ptr);                // g_Z norm + out + colsum
    gemm_quant_kernel<<<dim3(DIM / 128, NTOK / 128), 256>>>(emb, x, q_ptr);
    finalize_kernel<<<1, 512>>>(loss_ptr, ppl_ptr);
}